// round 1
// baseline (speedup 1.0000x reference)
#include <cuda_runtime.h>
#include <math.h>

// Problem constants (B=1, CX=CY=CZ=32, QX=QY=QZ=48)
#define QTOT   110592      // 48^3
#define CTXC   96
#define NCOORD 60
#define NIN0   156         // CTXC + NCOORD
#define OUTC   45
#define PTS    8           // points per CTA
#define ROWS   64          // PTS * 8 corners
#define XSTR   97          // padded stride for 96-wide activation buffers
#define CSTR   61          // padded stride for coord features
#define THREADS 256

// Shared memory layout (in floats); all offsets multiple of 4 for float4 copies
#define OFF_X    0
#define OFF_HA   (ROWS*XSTR)            // 6208
#define OFF_HB   (2*ROWS*XSTR)          // 12416
#define OFF_C    (3*ROWS*XSTR)          // 18624
#define OFF_W    (OFF_C + ROWS*CSTR)    // 22528
#define OFF_B    (OFF_W + NIN0*CTXC)    // 37504
#define OFF_W8   (OFF_B + CTXC)         // 37600
#define OFF_PT   (OFF_W8 + ROWS)        // 37664  (t factors, 24)
#define OFF_PQ   (OFF_PT + 24)          // ptQ, 24
#define OFF_PR   (OFF_PQ + 24)          // raw rel000, 24
#define OFF_MISC (OFF_PR + 24)          // qv[3], vox[3], min[3]
#define OFF_INT  (OFF_MISC + 12)        // ints: near[24], rowBase[64]
#define SMEM_FLOATS (OFF_INT + 24 + 64)
#define SMEM_BYTES  (SMEM_FLOATS * 4)

__device__ unsigned int g_min_enc[3];

__device__ __forceinline__ unsigned fenc(float f) {
    unsigned u = __float_as_uint(f);
    return (u & 0x80000000u) ? ~u : (u | 0x80000000u);
}
__device__ __forceinline__ float fdec(unsigned e) {
    return __uint_as_float((e & 0x80000000u) ? (e ^ 0x80000000u) : ~e);
}
__device__ __forceinline__ float silu(float x) {
    return x * (1.0f / (1.0f + __expf(-x)));
}

__global__ void init_min_kernel() {
    if (threadIdx.x < 3) g_min_enc[threadIdx.x] = 0xFFFFFFFFu;
}

// Global min over raw rel000 (pre-clamp) per dim. Clamp is applied later (monotone).
__global__ void min_kernel(const float* __restrict__ ext, const float* __restrict__ qc) {
    int p = blockIdx.x * blockDim.x + threadIdx.x;
    float raw[3] = {1e30f, 1e30f, 1e30f};
    if (p < QTOT) {
        int ni[3];
        float q[3];
#pragma unroll
        for (int d = 0; d < 3; d++) {
            float o = ext[d * 32768];
            float v = fabsf(ext[d * 32768 + 1057] - o);
            q[d] = qc[d * QTOT + p];
            int n = __float2int_rn((q[d] - o) / v);
            ni[d] = min(max(n, 0), 30);
        }
#pragma unroll
        for (int d = 0; d < 3; d++) {
            float cc = ext[d * 32768 + ni[0] * 1024 + ni[1] * 32 + ni[2]];
            raw[d] = cc - q[d];
        }
    }
#pragma unroll
    for (int off = 16; off; off >>= 1) {
#pragma unroll
        for (int d = 0; d < 3; d++)
            raw[d] = fminf(raw[d], __shfl_down_sync(0xffffffffu, raw[d], off));
    }
    if ((threadIdx.x & 31) == 0) {
#pragma unroll
        for (int d = 0; d < 3; d++)
            atomicMin(&g_min_enc[d], fenc(raw[d]));
    }
}

// Register-tiled matvec accumulate: 4 rows x NT neurons per thread.
template <int NT>
__device__ __forceinline__ void mv_acc(const float* __restrict__ in, int istr, int n_in,
                                       const float* __restrict__ w, int wstr, int n0,
                                       int r0, float (&acc)[4][NT]) {
#pragma unroll 4
    for (int i = 0; i < n_in; ++i) {
        float a0 = in[(r0 + 0) * istr + i];
        float a1 = in[(r0 + 1) * istr + i];
        float a2 = in[(r0 + 2) * istr + i];
        float a3 = in[(r0 + 3) * istr + i];
        const float* wr = w + i * wstr + n0;
#pragma unroll
        for (int v = 0; v < NT; ++v) {
            float wv = wr[v];
            acc[0][v] = fmaf(a0, wv, acc[0][v]);
            acc[1][v] = fmaf(a1, wv, acc[1][v]);
            acc[2][v] = fmaf(a2, wv, acc[2][v]);
            acc[3][v] = fmaf(a3, wv, acc[3][v]);
        }
    }
}

__device__ __forceinline__ void loadW4(float* dst, const float* __restrict__ src, int n, int tid) {
    const float4* s4 = (const float4*)src;
    float4* d4 = (float4*)dst;
    for (int i = tid; i < (n >> 2); i += THREADS) d4[i] = s4[i];
}

__global__ __launch_bounds__(THREADS, 1) void main_kernel(
    const float* __restrict__ ctxv, const float* __restrict__ ext,
    const float* __restrict__ qvs, const float* __restrict__ qc,
    const float* __restrict__ w00, const float* __restrict__ b00,
    const float* __restrict__ w01, const float* __restrict__ b01,
    const float* __restrict__ w02, const float* __restrict__ b02,
    const float* __restrict__ w10, const float* __restrict__ b10,
    const float* __restrict__ w11, const float* __restrict__ b11,
    const float* __restrict__ w12, const float* __restrict__ b12,
    const float* __restrict__ pw, const float* __restrict__ pb,
    float* __restrict__ out) {
    extern __shared__ float sm[];
    float* xS = sm + OFF_X;
    float* hA = sm + OFF_HA;
    float* hB = sm + OFF_HB;
    float* coordS = sm + OFF_C;
    float* wS = sm + OFF_W;
    float* bS = sm + OFF_B;
    float* w8S = sm + OFF_W8;
    float* ptT = sm + OFF_PT;
    float* ptQ = sm + OFF_PQ;
    float* ptR = sm + OFF_PR;
    float* qvS = sm + OFF_MISC;
    float* voxS = qvS + 3;
    float* minS = voxS + 3;
    int* nearS = (int*)(sm + OFF_INT);
    int* rowBaseS = nearS + 24;

    const int tid = threadIdx.x;
    const int pbase = blockIdx.x * PTS;

    // ---- Region 1: per-dim constants + per-point nearest ----
    if (tid < 3) {
        float o = ext[tid * 32768];
        qvS[tid] = qvs[tid];
        voxS[tid] = fabsf(ext[tid * 32768 + 1057] - o);
        minS[tid] = fdec(g_min_enc[tid]);
    }
    if (tid < 24) {
        int pt = tid / 3, d = tid - pt * 3;
        float o = ext[d * 32768];
        float v = fabsf(ext[d * 32768 + 1057] - o);
        float q = qc[d * QTOT + pbase + pt];
        int n = __float2int_rn((q - o) / v);
        nearS[tid] = min(max(n, 0), 30);
        ptQ[tid] = q;
    }
    __syncthreads();

    // ---- Region 2: raw rel000, trilinear t, per-row gather base ----
    if (tid < 24) {
        int pt = tid / 3, d = tid - pt * 3;
        float cc = ext[d * 32768 + nearS[pt * 3] * 1024 + nearS[pt * 3 + 1] * 32 + nearS[pt * 3 + 2]];
        float raw = cc - ptQ[tid];
        ptR[tid] = raw;
        float v = voxS[d];
        float clampc = fmaf(v, -0.5f, 1e-7f);
        float rel0 = fmaxf(raw, clampc);
        float g = fminf(fmaxf((rel0 - 0.5f) * 2.0f, -1.0f + 1e-7f), 1.0f - 1e-7f);
        ptT[tid] = (g + 1.0f) * 0.5f;
    }
    if (tid < ROWS) {
        int pt = tid >> 3, cn = tid & 7;
        int ix = nearS[pt * 3 + 0] + ((cn >> 2) & 1);
        int iy = nearS[pt * 3 + 1] + ((cn >> 1) & 1);
        int iz = nearS[pt * 3 + 2] + (cn & 1);
        rowBaseS[tid] = ix * 1024 + iy * 32 + iz;
    }
    __syncthreads();

    // ---- Region 3: trilinear weights, coord features, context gather ----
    if (tid < ROWS) {
        int pt = tid >> 3, cn = tid & 7;
        // Reference mapping: corner i (dim0) uses t[dim2], j uses t[dim1], k uses t[dim0]
        float wi = ((cn >> 2) & 1) ? ptT[pt * 3 + 2] : 1.0f - ptT[pt * 3 + 2];
        float wj = ((cn >> 1) & 1) ? ptT[pt * 3 + 1] : 1.0f - ptT[pt * 3 + 1];
        float wk = (cn & 1) ? ptT[pt * 3 + 0] : 1.0f - ptT[pt * 3 + 0];
        w8S[tid] = wi * wj * wk;
    }
    if (tid < ROWS * 3) {
        int row = tid / 3, d = tid - row * 3;
        int pt = row >> 3, cn = row & 7;
        int off = (d == 0) ? ((cn >> 2) & 1) : (d == 1) ? ((cn >> 1) & 1) : (cn & 1);
        float v = voxS[d];
        float clampc = fmaf(v, -0.5f, 1e-7f);
        float raw = ptR[pt * 3 + d] + (float)off * v;
        float rel = fmaxf(raw, clampc);
        float rmin = fmaxf(minS[d] + (float)off * v, clampc);
        float rn = (rel - rmin) / (1.5f * v);
        float cc = ext[d * 32768 + rowBaseS[row]];
        float* cf = coordS + row * CSTR;
        cf[0 + d] = qvS[d];
        cf[3 + d] = cc;
        cf[6 + d] = ptQ[pt * 3 + d];
        cf[9 + d] = rn;
        const float TWO_PI = 6.2831853071795864769f;
#pragma unroll
        for (int f = 0; f < 8; ++f) {
            float fr = exp2f((float)f * 0.29024101186092026f);  // 5^(f/8)
            float ang = TWO_PI * rn * fr;
            cf[12 + d * 16 + f] = sinf(ang);
            cf[12 + d * 16 + 8 + f] = cosf(ang);
        }
    }
    for (int idx = tid; idx < ROWS * CTXC; idx += THREADS) {
        int c = idx >> 6, row = idx & 63;
        xS[row * XSTR + c] = ctxv[c * 32768 + rowBaseS[row]];
    }
    __syncthreads();

    // ---- MLP: 2 skip blocks of (156->96, 96->96, 96->96), all silu ----
    const int ng = tid & 15;
    const int rg = tid >> 4;
    const int r0 = rg * 4;
    const int n06 = ng * 6;

    const float* WP[6] = {w00, w01, w02, w10, w11, w12};
    const float* BP[6] = {b00, b01, b02, b10, b11, b12};

#pragma unroll 1
    for (int blk = 0; blk < 2; ++blk) {
        // Layer 0: [x ; coord] @ W0 + b0, silu -> hA
        loadW4(wS, WP[blk * 3 + 0], NIN0 * CTXC, tid);
        loadW4(bS, BP[blk * 3 + 0], CTXC, tid);
        __syncthreads();
        {
            float acc[4][6];
#pragma unroll
            for (int v = 0; v < 6; ++v) {
                float bb = bS[n06 + v];
                acc[0][v] = bb; acc[1][v] = bb; acc[2][v] = bb; acc[3][v] = bb;
            }
            mv_acc<6>(xS, XSTR, CTXC, wS, CTXC, n06, r0, acc);
            mv_acc<6>(coordS, CSTR, NCOORD, wS + CTXC * CTXC, CTXC, n06, r0, acc);
#pragma unroll
            for (int u = 0; u < 4; ++u)
#pragma unroll
                for (int v = 0; v < 6; ++v)
                    hA[(r0 + u) * XSTR + n06 + v] = silu(acc[u][v]);
        }
        __syncthreads();

        // Layer 1: hA -> hB
        loadW4(wS, WP[blk * 3 + 1], CTXC * CTXC, tid);
        loadW4(bS, BP[blk * 3 + 1], CTXC, tid);
        __syncthreads();
        {
            float acc[4][6];
#pragma unroll
            for (int v = 0; v < 6; ++v) {
                float bb = bS[n06 + v];
                acc[0][v] = bb; acc[1][v] = bb; acc[2][v] = bb; acc[3][v] = bb;
            }
            mv_acc<6>(hA, XSTR, CTXC, wS, CTXC, n06, r0, acc);
#pragma unroll
            for (int u = 0; u < 4; ++u)
#pragma unroll
                for (int v = 0; v < 6; ++v)
                    hB[(r0 + u) * XSTR + n06 + v] = silu(acc[u][v]);
        }
        __syncthreads();

        // Layer 2: hB -> hA
        loadW4(wS, WP[blk * 3 + 2], CTXC * CTXC, tid);
        loadW4(bS, BP[blk * 3 + 2], CTXC, tid);
        __syncthreads();
        {
            float acc[4][6];
#pragma unroll
            for (int v = 0; v < 6; ++v) {
                float bb = bS[n06 + v];
                acc[0][v] = bb; acc[1][v] = bb; acc[2][v] = bb; acc[3][v] = bb;
            }
            mv_acc<6>(hB, XSTR, CTXC, wS, CTXC, n06, r0, acc);
#pragma unroll
            for (int u = 0; u < 4; ++u)
#pragma unroll
                for (int v = 0; v < 6; ++v)
                    hA[(r0 + u) * XSTR + n06 + v] = silu(acc[u][v]);
        }
        __syncthreads();

        // Skip add: x += h
        for (int idx = tid; idx < ROWS * CTXC; idx += THREADS) {
            int row = idx / CTXC, c = idx - row * CTXC;
            xS[row * XSTR + c] += hA[row * XSTR + c];
        }
        __syncthreads();
    }

    // ---- Post layer: 96 -> 45 (padded to 48), no activation ----
    for (int idx = tid; idx < CTXC * 48; idx += THREADS) {
        int i = idx / 48, c = idx - i * 48;
        wS[idx] = (c < OUTC) ? pw[i * OUTC + c] : 0.0f;
    }
    if (tid < 48) bS[tid] = (tid < OUTC) ? pb[tid] : 0.0f;
    __syncthreads();
    {
        const int n03 = ng * 3;
        float acc[4][3];
#pragma unroll
        for (int v = 0; v < 3; ++v) {
            float bb = bS[n03 + v];
            acc[0][v] = bb; acc[1][v] = bb; acc[2][v] = bb; acc[3][v] = bb;
        }
        mv_acc<3>(xS, XSTR, CTXC, wS, 48, n03, r0, acc);
#pragma unroll
        for (int u = 0; u < 4; ++u)
#pragma unroll
            for (int v = 0; v < 3; ++v)
                hB[(r0 + u) * XSTR + n03 + v] = acc[u][v];
    }
    __syncthreads();

    // ---- Trilinear combine over 8 corners, write output ----
    for (int idx = tid; idx < OUTC * PTS; idx += THREADS) {
        int col = idx >> 3, pt = idx & 7;
        float a = 0.0f;
#pragma unroll
        for (int c8 = 0; c8 < 8; ++c8) {
            int row = pt * 8 + c8;
            a = fmaf(w8S[row], hB[row * XSTR + col], a);
        }
        out[col * QTOT + pbase + pt] = a;
    }
}

extern "C" void kernel_launch(void* const* d_in, const int* in_sizes, int n_in,
                              void* d_out, int out_size) {
    const float* ctxv = (const float*)d_in[0];   // context_v (1,96,32,32,32)
    const float* ext  = (const float*)d_in[1];   // context_spatial_extent (1,3,32,32,32)
    const float* qvs  = (const float*)d_in[2];   // query_vox_size (1,3)
    const float* qc   = (const float*)d_in[3];   // query_coord (1,3,48,48,48)
    const float* w00 = (const float*)d_in[4];
    const float* b00 = (const float*)d_in[5];
    const float* w01 = (const float*)d_in[6];
    const float* b01 = (const float*)d_in[7];
    const float* w02 = (const float*)d_in[8];
    const float* b02 = (const float*)d_in[9];
    const float* w10 = (const float*)d_in[10];
    const float* b10 = (const float*)d_in[11];
    const float* w11 = (const float*)d_in[12];
    const float* b11 = (const float*)d_in[13];
    const float* w12 = (const float*)d_in[14];
    const float* b12 = (const float*)d_in[15];
    const float* pw  = (const float*)d_in[16];
    const float* pb  = (const float*)d_in[17];
    float* out = (float*)d_out;

    cudaFuncSetAttribute(main_kernel, cudaFuncAttributeMaxDynamicSharedMemorySize, SMEM_BYTES);

    init_min_kernel<<<1, 32>>>();
    min_kernel<<<QTOT / 256, 256>>>(ext, qc);
    main_kernel<<<QTOT / PTS, THREADS, SMEM_BYTES>>>(
        ctxv, ext, qvs, qc,
        w00, b00, w01, b01, w02, b02,
        w10, b10, w11, b11, w12, b12,
        pw, pb, out);
}